// round 2
// baseline (speedup 1.0000x reference)
#include <cuda_runtime.h>

#define N_NODES 100000
#define N_EDGES 1600000
#define C_IN    128
#define HEADS   4
#define HEAD_D  32
#define C_OUT   128   // HEADS*HEAD_D

// ---- scratch (static __device__ arrays: no allocation allowed) ----
__device__ float    g_xw[(size_t)N_NODES * C_OUT];      // 51.2 MB, fits L2
__device__ float    g_asrc[N_NODES * HEADS];
__device__ float    g_adst[N_NODES * HEADS];
__device__ unsigned g_amax_enc[N_NODES * HEADS];
__device__ float    g_amax[N_NODES * HEADS];
__device__ float    g_asum[N_NODES * HEADS];
__device__ int2     g_edge[N_EDGES];                    // packed (row, col)
__device__ int      g_is64;

// order-preserving float<->uint encoding for atomicMax on floats
__device__ __forceinline__ unsigned fenc(float f) {
    unsigned u = __float_as_uint(f);
    return (u & 0x80000000u) ? ~u : (u | 0x80000000u);
}
__device__ __forceinline__ float fdec(unsigned e) {
    return (e & 0x80000000u) ? __uint_as_float(e & 0x7FFFFFFFu)
                             : __uint_as_float(~e);
}

__device__ __forceinline__ void red_add_v4(float* p, float4 v) {
    asm volatile("red.global.v4.f32.add [%0], {%1, %2, %3, %4};"
                 :: "l"(p), "f"(v.x), "f"(v.y), "f"(v.z), "f"(v.w) : "memory");
}

// ---- detect int32 vs int64 edge_index (values < 2^31, so int64 high words are 0)
__global__ void k_detect(const unsigned* __restrict__ w) {
    __shared__ int nz;
    if (threadIdx.x == 0) nz = 0;
    __syncthreads();
    // scan odd 32-bit words of the first 2048 (64-bit-candidate) elements
    int bad = 0;
    for (int i = threadIdx.x; i < 2048; i += blockDim.x)
        if (w[2 * i + 1] != 0u) bad = 1;
    if (bad) atomicOr(&nz, 1);
    __syncthreads();
    if (threadIdx.x == 0) g_is64 = (nz == 0);
}

// ---- normalize edge_index into packed int2 (row, col) ----
__global__ void k_convert(const void* __restrict__ ei_raw) {
    int e = blockIdx.x * blockDim.x + threadIdx.x;
    if (e >= N_EDGES) return;
    int r, c;
    if (g_is64) {
        const long long* p = (const long long*)ei_raw;
        r = (int)p[e];
        c = (int)p[N_EDGES + e];
    } else {
        const int* p = (const int*)ei_raw;
        r = p[e];
        c = p[N_EDGES + e];
    }
    g_edge[e] = make_int2(r, c);
}

// ---- 0) zero output + per-(node,head) accumulators (runs every replay) ----
__global__ void k_init(float* __restrict__ out) {
    int i = blockIdx.x * blockDim.x + threadIdx.x;
    int stride = gridDim.x * blockDim.x;
    float4 z = make_float4(0.f, 0.f, 0.f, 0.f);
    for (int j = i; j < N_NODES * C_OUT / 4; j += stride)
        reinterpret_cast<float4*>(out)[j] = z;
    for (int j = i; j < N_NODES * HEADS; j += stride) {
        g_asum[j] = 0.f;
        g_amax_enc[j] = 0u;   // < fenc(any finite value) => "untouched"
    }
}

// ---- 1) xw = x @ W  and  a_src/a_dst = einsum(xw, att) ----
__global__ void __launch_bounds__(128) k_gemm(
    const float* __restrict__ x, const float* __restrict__ W,
    const float* __restrict__ att_src, const float* __restrict__ att_dst)
{
    __shared__ float xs[32 * C_IN];            // 16 KB
    const int row0 = blockIdx.x * 32;
    const int tid  = threadIdx.x;              // = output column o

    const float4* xg  = reinterpret_cast<const float4*>(x + (size_t)row0 * C_IN);
    float4*       xs4 = reinterpret_cast<float4*>(xs);
    #pragma unroll
    for (int i = tid; i < 32 * C_IN / 4; i += 128) xs4[i] = xg[i];
    __syncthreads();

    float acc[32];
    #pragma unroll
    for (int r = 0; r < 32; ++r) acc[r] = 0.f;

    #pragma unroll 4
    for (int k = 0; k < C_IN; ++k) {
        float w = __ldg(&W[k * C_OUT + tid]);
        #pragma unroll
        for (int r = 0; r < 32; ++r) acc[r] += xs[r * C_IN + k] * w;
    }

    #pragma unroll
    for (int r = 0; r < 32; ++r)
        g_xw[(size_t)(row0 + r) * C_OUT + tid] = acc[r];

    const int lane = tid & 31;
    const int h    = tid >> 5;
    const float aw_s = att_src[h * HEAD_D + lane];
    const float aw_d = att_dst[h * HEAD_D + lane];
    #pragma unroll
    for (int r = 0; r < 32; ++r) {
        float vs = acc[r] * aw_s;
        float vd = acc[r] * aw_d;
        #pragma unroll
        for (int o = 16; o > 0; o >>= 1) {
            vs += __shfl_down_sync(0xFFFFFFFFu, vs, o);
            vd += __shfl_down_sync(0xFFFFFFFFu, vd, o);
        }
        if (lane == 0) {
            g_asrc[(row0 + r) * HEADS + h] = vs;
            g_adst[(row0 + r) * HEADS + h] = vd;
        }
    }
}

// ---- 2) segment max of leaky_relu(a_src[row]+a_dst[col]) over row ----
__global__ void k_edge_max() {
    int e = blockIdx.x * blockDim.x + threadIdx.x;
    if (e >= N_EDGES) return;
    int2 rc = g_edge[e];
    float4 s = *reinterpret_cast<const float4*>(g_asrc + rc.x * 4);
    float4 d = *reinterpret_cast<const float4*>(g_adst + rc.y * 4);
    float v;
    v = s.x + d.x; v = v > 0.f ? v : 0.2f * v; atomicMax(&g_amax_enc[rc.x * 4 + 0], fenc(v));
    v = s.y + d.y; v = v > 0.f ? v : 0.2f * v; atomicMax(&g_amax_enc[rc.x * 4 + 1], fenc(v));
    v = s.z + d.z; v = v > 0.f ? v : 0.2f * v; atomicMax(&g_amax_enc[rc.x * 4 + 2], fenc(v));
    v = s.w + d.w; v = v > 0.f ? v : 0.2f * v; atomicMax(&g_amax_enc[rc.x * 4 + 3], fenc(v));
}

// ---- 3) decode amax (empty segment -> 0, matches reference) ----
__global__ void k_fix_amax() {
    int i = blockIdx.x * blockDim.x + threadIdx.x;
    if (i >= N_NODES * HEADS) return;
    unsigned e = g_amax_enc[i];
    g_amax[i] = (e == 0u) ? 0.f : fdec(e);
}

// ---- 4) fused exp + sum + weighted scatter: one warp per edge ----
__global__ void __launch_bounds__(256) k_agg(float* __restrict__ out) {
    int gid  = blockIdx.x * blockDim.x + threadIdx.x;
    int e    = gid >> 5;
    if (e >= N_EDGES) return;
    int lane = gid & 31;
    int2 rc  = g_edge[e];                    // broadcast within warp
    int h    = lane >> 3;                    // 8 lanes per head

    float lr = g_asrc[rc.x * 4 + h] + g_adst[rc.y * 4 + h];
    lr = lr > 0.f ? lr : 0.2f * lr;
    float ex = __expf(lr - g_amax[rc.x * 4 + h]);   // exponent <= 0

    if ((lane & 7) == 0) atomicAdd(&g_asum[rc.x * 4 + h], ex);

    float4 v = *reinterpret_cast<const float4*>(g_xw + (size_t)rc.y * C_OUT + lane * 4);
    v.x *= ex; v.y *= ex; v.z *= ex; v.w *= ex;
    red_add_v4(out + (size_t)rc.x * C_OUT + lane * 4, v);
}

// ---- 5) normalize: out /= (asum + 1e-16) ----
__global__ void k_final(float* __restrict__ out) {
    int i = blockIdx.x * blockDim.x + threadIdx.x;
    if (i >= N_NODES * C_OUT) return;
    int n = i >> 7;
    int h = (i >> 5) & 3;
    out[i] = out[i] / (g_asum[n * 4 + h] + 1e-16f);
}

extern "C" void kernel_launch(void* const* d_in, const int* in_sizes, int n_in,
                              void* d_out, int out_size)
{
    int ix = -1, iw = -1, ia1 = -1, ia2 = -1, iei = -1;
    for (int i = 0; i < n_in; ++i) {
        int s = in_sizes[i];
        if      (s == N_NODES * C_IN && ix < 0)  ix = i;
        else if (s == C_IN * C_OUT   && iw < 0)  iw = i;
        else if (s == HEADS * HEAD_D) { if (ia1 < 0) ia1 = i; else if (ia2 < 0) ia2 = i; }
        else if (s == 2 * N_EDGES    && iei < 0) iei = i;
    }
    const float* x   = (const float*)d_in[ix];
    const float* W   = (const float*)d_in[iw];
    const float* as_ = (const float*)d_in[ia1];
    const float* ad_ = (const float*)d_in[ia2];
    const void*  ei  = d_in[iei];
    float*       out = (float*)d_out;

    k_detect<<<1, 256>>>((const unsigned*)ei);
    k_convert<<<(N_EDGES + 255) / 256, 256>>>(ei);
    k_init<<<1024, 256>>>(out);
    k_gemm<<<N_NODES / 32, 128>>>(x, W, as_, ad_);
    k_edge_max<<<(N_EDGES + 255) / 256, 256>>>();
    k_fix_amax<<<(N_NODES * HEADS + 255) / 256, 256>>>();
    k_agg<<<(N_EDGES * 32) / 256, 256>>>(out);
    k_final<<<(N_NODES * C_OUT + 255) / 256, 256>>>(out);
}

// round 3
// speedup vs baseline: 1.2976x; 1.2976x over previous
#include <cuda_runtime.h>

#define N_NODES 100000
#define N_EDGES 1600000
#define C_IN    128
#define HEADS   4
#define HEAD_D  32
#define C_OUT   128   // HEADS*HEAD_D

// ---- scratch (static __device__ arrays: no allocation allowed) ----
__device__ float g_xw[(size_t)N_NODES * C_OUT];      // 51.2 MB
__device__ float g_asrc[N_NODES * HEADS];
__device__ float g_adst[N_NODES * HEADS];
__device__ float g_asum[N_NODES * HEADS];
__device__ int2  g_edge[N_EDGES];                    // packed (row, col)
__device__ int   g_is64;

__device__ __forceinline__ void red_add_v4(float* p, float4 v) {
    asm volatile("red.global.v4.f32.add [%0], {%1, %2, %3, %4};"
                 :: "l"(p), "f"(v.x), "f"(v.y), "f"(v.z), "f"(v.w) : "memory");
}

// ---- detect int32 vs int64 edge_index (node ids < 2^31 => int64 high words all 0)
__global__ void k_detect(const unsigned* __restrict__ w) {
    __shared__ int nz;
    if (threadIdx.x == 0) nz = 0;
    __syncthreads();
    int bad = 0;
    for (int i = threadIdx.x; i < 2048; i += blockDim.x)
        if (w[2 * i + 1] != 0u) bad = 1;
    if (bad) atomicOr(&nz, 1);
    __syncthreads();
    if (threadIdx.x == 0) g_is64 = (nz == 0);
}

// ---- normalize edge_index into packed int2 (row, col) ----
__global__ void k_convert(const void* __restrict__ ei_raw) {
    int e = blockIdx.x * blockDim.x + threadIdx.x;
    if (e >= N_EDGES) return;
    int r, c;
    if (g_is64) {
        const long long* p = (const long long*)ei_raw;
        r = (int)p[e];
        c = (int)p[N_EDGES + e];
    } else {
        const int* p = (const int*)ei_raw;
        r = p[e];
        c = p[N_EDGES + e];
    }
    g_edge[e] = make_int2(r, c);
}

// ---- 0) zero output + per-(node,head) accumulators (runs every replay) ----
__global__ void k_init(float* __restrict__ out) {
    int i = blockIdx.x * blockDim.x + threadIdx.x;
    int stride = gridDim.x * blockDim.x;
    float4 z = make_float4(0.f, 0.f, 0.f, 0.f);
    for (int j = i; j < N_NODES * C_OUT / 4; j += stride)
        reinterpret_cast<float4*>(out)[j] = z;
    for (int j = i; j < N_NODES * HEADS; j += stride)
        g_asum[j] = 0.f;
}

// ---- 1) xw = x @ W and attention logits. 128x128 tile, 8x8 per thread ----
#define BM 128
#define BK 8
#define XS_PAD 132
__global__ void __launch_bounds__(256) k_gemm(
    const float* __restrict__ x, const float* __restrict__ W,
    const float* __restrict__ att_src, const float* __restrict__ att_dst)
{
    __shared__ float xsT[BK][XS_PAD];   // k-major, padded (conflict-free)
    __shared__ float ws[BK][C_OUT];

    const int t    = threadIdx.x;
    const int tx   = t & 15;            // 16 col-groups of 8
    const int ty   = t >> 4;            // 16 row-groups of 8
    const int row0 = blockIdx.x * BM;

    float acc[8][8];
    #pragma unroll
    for (int i = 0; i < 8; ++i)
        #pragma unroll
        for (int j = 0; j < 8; ++j) acc[i][j] = 0.f;

    // per-chunk load indices
    const int xr  = t >> 1;             // row within tile (0..127)
    const int xkq = (t & 1) * 4;        // k offset (0 or 4)
    const int wk  = t >> 5;             // k row (0..7)
    const int wn  = (t & 31) * 4;       // col (0..124)
    const int xrow = min(row0 + xr, N_NODES - 1);   // clamp; writes guarded

    for (int kt = 0; kt < C_IN / BK; ++kt) {
        float4 xv = *reinterpret_cast<const float4*>(x + (size_t)xrow * C_IN + kt * BK + xkq);
        float4 wv = *reinterpret_cast<const float4*>(W + (size_t)(kt * BK + wk) * C_OUT + wn);
        __syncthreads();
        xsT[xkq + 0][xr] = xv.x;
        xsT[xkq + 1][xr] = xv.y;
        xsT[xkq + 2][xr] = xv.z;
        xsT[xkq + 3][xr] = xv.w;
        *reinterpret_cast<float4*>(&ws[wk][wn]) = wv;
        __syncthreads();

        #pragma unroll
        for (int kk = 0; kk < BK; ++kk) {
            float xa[8], wa[8];
            *reinterpret_cast<float4*>(xa)     = *reinterpret_cast<const float4*>(&xsT[kk][ty * 8]);
            *reinterpret_cast<float4*>(xa + 4) = *reinterpret_cast<const float4*>(&xsT[kk][ty * 8 + 4]);
            *reinterpret_cast<float4*>(wa)     = *reinterpret_cast<const float4*>(&ws[kk][tx * 8]);
            *reinterpret_cast<float4*>(wa + 4) = *reinterpret_cast<const float4*>(&ws[kk][tx * 8 + 4]);
            #pragma unroll
            for (int i = 0; i < 8; ++i)
                #pragma unroll
                for (int j = 0; j < 8; ++j)
                    acc[i][j] += xa[i] * wa[j];
        }
    }

    // write xw tile
    #pragma unroll
    for (int i = 0; i < 8; ++i) {
        int row = row0 + ty * 8 + i;
        if (row < N_NODES) {
            float4* p = reinterpret_cast<float4*>(g_xw + (size_t)row * C_OUT + tx * 8);
            p[0] = make_float4(acc[i][0], acc[i][1], acc[i][2], acc[i][3]);
            p[1] = make_float4(acc[i][4], acc[i][5], acc[i][6], acc[i][7]);
        }
    }

    // attention logits: thread's 8 cols live in head h = tx>>2, offset (tx&3)*8
    const int h    = tx >> 2;
    const int joff = (tx & 3) * 8;
    float ats[8], atd[8];
    #pragma unroll
    for (int j = 0; j < 8; ++j) {
        ats[j] = att_src[h * HEAD_D + joff + j];
        atd[j] = att_dst[h * HEAD_D + joff + j];
    }
    #pragma unroll
    for (int i = 0; i < 8; ++i) {
        int row = row0 + ty * 8 + i;
        float vs = 0.f, vd = 0.f;
        #pragma unroll
        for (int j = 0; j < 8; ++j) { vs += acc[i][j] * ats[j]; vd += acc[i][j] * atd[j]; }
        vs += __shfl_down_sync(0xFFFFFFFFu, vs, 2);
        vs += __shfl_down_sync(0xFFFFFFFFu, vs, 1);
        vd += __shfl_down_sync(0xFFFFFFFFu, vd, 2);
        vd += __shfl_down_sync(0xFFFFFFFFu, vd, 1);
        if ((tx & 3) == 0 && row < N_NODES) {
            g_asrc[row * HEADS + h] = vs;
            g_adst[row * HEADS + h] = vd;
        }
    }
}

// ---- 2) fused exp + sum + weighted scatter: one warp per edge ----
// Softmax shift-invariance: normalization deferred to k_final, so no max pass.
__global__ void __launch_bounds__(256) k_agg(float* __restrict__ out) {
    int gid  = blockIdx.x * blockDim.x + threadIdx.x;
    int e    = gid >> 5;
    if (e >= N_EDGES) return;
    int lane = gid & 31;
    int2 rc  = g_edge[e];                    // broadcast within warp
    int h    = lane >> 3;                    // 8 lanes per head

    float lr = g_asrc[rc.x * HEADS + h] + g_adst[rc.y * HEADS + h];
    lr = lr > 0.f ? lr : 0.2f * lr;
    float ex = __expf(lr);

    if ((lane & 7) == 0) atomicAdd(&g_asum[rc.x * HEADS + h], ex);

    float4 v = *reinterpret_cast<const float4*>(g_xw + (size_t)rc.y * C_OUT + lane * 4);
    v.x *= ex; v.y *= ex; v.z *= ex; v.w *= ex;
    red_add_v4(out + (size_t)rc.x * C_OUT + lane * 4, v);
}

// ---- 3) normalize: out /= (asum + 1e-16) ----
__global__ void k_final(float* __restrict__ out) {
    int i = blockIdx.x * blockDim.x + threadIdx.x;
    if (i >= N_NODES * C_OUT) return;
    int n = i >> 7;
    int h = (i >> 5) & 3;
    out[i] = out[i] / (g_asum[n * 4 + h] + 1e-16f);
}

extern "C" void kernel_launch(void* const* d_in, const int* in_sizes, int n_in,
                              void* d_out, int out_size)
{
    int ix = -1, iw = -1, ia1 = -1, ia2 = -1, iei = -1;
    for (int i = 0; i < n_in; ++i) {
        int s = in_sizes[i];
        if      (s == N_NODES * C_IN && ix < 0)  ix = i;
        else if (s == C_IN * C_OUT   && iw < 0)  iw = i;
        else if (s == HEADS * HEAD_D) { if (ia1 < 0) ia1 = i; else if (ia2 < 0) ia2 = i; }
        else if (s == 2 * N_EDGES    && iei < 0) iei = i;
    }
    const float* x   = (const float*)d_in[ix];
    const float* W   = (const float*)d_in[iw];
    const float* as_ = (const float*)d_in[ia1];
    const float* ad_ = (const float*)d_in[ia2];
    const void*  ei  = d_in[iei];
    float*       out = (float*)d_out;

    k_detect<<<1, 256>>>((const unsigned*)ei);
    k_convert<<<(N_EDGES + 255) / 256, 256>>>(ei);
    k_init<<<1024, 256>>>(out);
    k_gemm<<<(N_NODES + BM - 1) / BM, 256>>>(x, W, as_, ad_);
    k_agg<<<(N_EDGES * 32) / 256, 256>>>(out);
    k_final<<<(N_NODES * C_OUT + 255) / 256, 256>>>(out);
}

// round 4
// speedup vs baseline: 2.2098x; 1.7031x over previous
#include <cuda_runtime.h>

#define N_NODES 100000
#define N_EDGES 1600000
#define C_IN    128
#define HEADS   4
#define HEAD_D  32
#define C_OUT   128
#define SCAN_BS 512
#define NBLK_SCAN ((N_NODES + SCAN_BS - 1) / SCAN_BS)   // 196

// ---- scratch ----
__device__ float g_xw[(size_t)N_NODES * C_OUT];      // 51.2 MB
__device__ float g_asrc[N_NODES * HEADS];
__device__ float g_adst[N_NODES * HEADS];
__device__ int2  g_edge[N_EDGES];
__device__ int   g_scol[N_EDGES];                    // cols grouped by row
__device__ int   g_deg[N_NODES];
__device__ int   g_rptr[N_NODES];
__device__ int   g_wp[N_NODES];
__device__ int   g_bsum[NBLK_SCAN];
__device__ int   g_is64;

// ---- detect int32 vs int64 edge_index ----
__global__ void k_detect(const unsigned* __restrict__ w) {
    __shared__ int nz;
    if (threadIdx.x == 0) nz = 0;
    __syncthreads();
    int bad = 0;
    for (int i = threadIdx.x; i < 2048; i += blockDim.x)
        if (w[2 * i + 1] != 0u) bad = 1;
    if (bad) atomicOr(&nz, 1);
    __syncthreads();
    if (threadIdx.x == 0) g_is64 = (nz == 0);
}

__global__ void k_zero_deg() {
    int i = blockIdx.x * blockDim.x + threadIdx.x;
    if (i < N_NODES) g_deg[i] = 0;
}

// ---- convert edge_index to int2 + row histogram ----
__global__ void k_convert_hist(const void* __restrict__ ei_raw) {
    int e = blockIdx.x * blockDim.x + threadIdx.x;
    if (e >= N_EDGES) return;
    int r, c;
    if (g_is64) {
        const long long* p = (const long long*)ei_raw;
        r = (int)p[e];
        c = (int)p[N_EDGES + e];
    } else {
        const int* p = (const int*)ei_raw;
        r = p[e];
        c = p[N_EDGES + e];
    }
    g_edge[e] = make_int2(r, c);
    atomicAdd(&g_deg[r], 1);
}

// ---- 3-kernel exclusive scan of g_deg -> g_rptr ----
__global__ void __launch_bounds__(SCAN_BS) k_scan1() {
    int i = blockIdx.x * SCAN_BS + threadIdx.x;
    int v = (i < N_NODES) ? g_deg[i] : 0;
    int lane = threadIdx.x & 31, wid = threadIdx.x >> 5;
    int inc = v;
    #pragma unroll
    for (int o = 1; o < 32; o <<= 1) {
        int t = __shfl_up_sync(0xFFFFFFFFu, inc, o);
        if (lane >= o) inc += t;
    }
    __shared__ int wsum[16];
    if (lane == 31) wsum[wid] = inc;
    __syncthreads();
    if (wid == 0 && lane < 16) {
        int s = wsum[lane];
        #pragma unroll
        for (int o = 1; o < 16; o <<= 1) {
            int t = __shfl_up_sync(0xFFFFu, s, o);
            if (lane >= o) s += t;
        }
        wsum[lane] = s;                       // inclusive warp totals
    }
    __syncthreads();
    int warpoff = (wid == 0) ? 0 : wsum[wid - 1];
    if (i < N_NODES) g_rptr[i] = warpoff + inc - v;
    if (threadIdx.x == SCAN_BS - 1) g_bsum[blockIdx.x] = warpoff + inc;
}
__global__ void k_scan2() {
    if (threadIdx.x == 0) {
        int s = 0;
        for (int b = 0; b < NBLK_SCAN; ++b) { int t = g_bsum[b]; g_bsum[b] = s; s += t; }
    }
}
__global__ void k_scan3() {
    int i = blockIdx.x * blockDim.x + threadIdx.x;
    if (i >= N_NODES) return;
    int v = g_rptr[i] + g_bsum[i >> 9];
    g_rptr[i] = v;
    g_wp[i]   = v;
}

// ---- group cols by row ----
__global__ void k_reorder() {
    int e = blockIdx.x * blockDim.x + threadIdx.x;
    if (e >= N_EDGES) return;
    int2 rc = g_edge[e];
    int slot = atomicAdd(&g_wp[rc.x], 1);
    g_scol[slot] = rc.y;
}

// ---- GEMM: xw = x @ W + attention logits (128x128 tile, 8x8/thread) ----
#define BM 128
#define BK 8
#define XS_PAD 132
__global__ void __launch_bounds__(256) k_gemm(
    const float* __restrict__ x, const float* __restrict__ W,
    const float* __restrict__ att_src, const float* __restrict__ att_dst)
{
    __shared__ float xsT[BK][XS_PAD];
    __shared__ float ws[BK][C_OUT];

    const int t    = threadIdx.x;
    const int tx   = t & 15;
    const int ty   = t >> 4;
    const int row0 = blockIdx.x * BM;

    float acc[8][8];
    #pragma unroll
    for (int i = 0; i < 8; ++i)
        #pragma unroll
        for (int j = 0; j < 8; ++j) acc[i][j] = 0.f;

    const int xr  = t >> 1;
    const int xkq = (t & 1) * 4;
    const int wk  = t >> 5;
    const int wn  = (t & 31) * 4;
    const int xrow = min(row0 + xr, N_NODES - 1);

    for (int kt = 0; kt < C_IN / BK; ++kt) {
        float4 xv = *reinterpret_cast<const float4*>(x + (size_t)xrow * C_IN + kt * BK + xkq);
        float4 wv = *reinterpret_cast<const float4*>(W + (size_t)(kt * BK + wk) * C_OUT + wn);
        __syncthreads();
        xsT[xkq + 0][xr] = xv.x;
        xsT[xkq + 1][xr] = xv.y;
        xsT[xkq + 2][xr] = xv.z;
        xsT[xkq + 3][xr] = xv.w;
        *reinterpret_cast<float4*>(&ws[wk][wn]) = wv;
        __syncthreads();

        #pragma unroll
        for (int kk = 0; kk < BK; ++kk) {
            float xa[8], wa[8];
            *reinterpret_cast<float4*>(xa)     = *reinterpret_cast<const float4*>(&xsT[kk][ty * 8]);
            *reinterpret_cast<float4*>(xa + 4) = *reinterpret_cast<const float4*>(&xsT[kk][ty * 8 + 4]);
            *reinterpret_cast<float4*>(wa)     = *reinterpret_cast<const float4*>(&ws[kk][tx * 8]);
            *reinterpret_cast<float4*>(wa + 4) = *reinterpret_cast<const float4*>(&ws[kk][tx * 8 + 4]);
            #pragma unroll
            for (int i = 0; i < 8; ++i)
                #pragma unroll
                for (int j = 0; j < 8; ++j)
                    acc[i][j] += xa[i] * wa[j];
        }
    }

    #pragma unroll
    for (int i = 0; i < 8; ++i) {
        int row = row0 + ty * 8 + i;
        if (row < N_NODES) {
            float4* p = reinterpret_cast<float4*>(g_xw + (size_t)row * C_OUT + tx * 8);
            p[0] = make_float4(acc[i][0], acc[i][1], acc[i][2], acc[i][3]);
            p[1] = make_float4(acc[i][4], acc[i][5], acc[i][6], acc[i][7]);
        }
    }

    const int h    = tx >> 2;
    const int joff = (tx & 3) * 8;
    float ats[8], atd[8];
    #pragma unroll
    for (int j = 0; j < 8; ++j) {
        ats[j] = att_src[h * HEAD_D + joff + j];
        atd[j] = att_dst[h * HEAD_D + joff + j];
    }
    #pragma unroll
    for (int i = 0; i < 8; ++i) {
        int row = row0 + ty * 8 + i;
        float vs = 0.f, vd = 0.f;
        #pragma unroll
        for (int j = 0; j < 8; ++j) { vs += acc[i][j] * ats[j]; vd += acc[i][j] * atd[j]; }
        vs += __shfl_down_sync(0xFFFFFFFFu, vs, 2);
        vs += __shfl_down_sync(0xFFFFFFFFu, vs, 1);
        vd += __shfl_down_sync(0xFFFFFFFFu, vd, 2);
        vd += __shfl_down_sync(0xFFFFFFFFu, vd, 1);
        if ((tx & 3) == 0 && row < N_NODES) {
            g_asrc[row * HEADS + h] = vs;
            g_adst[row * HEADS + h] = vd;
        }
    }
}

// ---- CSR aggregation: one warp per node, out written exactly once ----
// Softmax shift-invariance: exp(alpha)/sum(exp(alpha)), no max pass needed.
__global__ void __launch_bounds__(256) k_csr_agg(float* __restrict__ out) {
    int n = (blockIdx.x * blockDim.x + threadIdx.x) >> 5;
    if (n >= N_NODES) return;
    int lane = threadIdx.x & 31;
    int h    = lane >> 3;

    int start = g_rptr[n];
    int deg   = g_deg[n];
    float asrc_h = g_asrc[n * HEADS + h];

    float4 acc = make_float4(0.f, 0.f, 0.f, 0.f);
    float  asum = 0.f;

    int c_next = (deg > 0) ? g_scol[start] : 0;
    for (int j = 0; j < deg; ++j) {
        int c = c_next;
        if (j + 1 < deg) c_next = g_scol[start + j + 1];   // prefetch
        float lr = asrc_h + g_adst[c * HEADS + h];
        lr = lr > 0.f ? lr : 0.2f * lr;
        float ex = __expf(lr);
        float4 v = *reinterpret_cast<const float4*>(g_xw + (size_t)c * C_OUT + lane * 4);
        acc.x += ex * v.x;
        acc.y += ex * v.y;
        acc.z += ex * v.z;
        acc.w += ex * v.w;
        asum  += ex;
    }
    float inv = 1.f / (asum + 1e-16f);
    acc.x *= inv; acc.y *= inv; acc.z *= inv; acc.w *= inv;
    *reinterpret_cast<float4*>(out + (size_t)n * C_OUT + lane * 4) = acc;
}

extern "C" void kernel_launch(void* const* d_in, const int* in_sizes, int n_in,
                              void* d_out, int out_size)
{
    int ix = -1, iw = -1, ia1 = -1, ia2 = -1, iei = -1;
    for (int i = 0; i < n_in; ++i) {
        int s = in_sizes[i];
        if      (s == N_NODES * C_IN && ix < 0)  ix = i;
        else if (s == C_IN * C_OUT   && iw < 0)  iw = i;
        else if (s == HEADS * HEAD_D) { if (ia1 < 0) ia1 = i; else if (ia2 < 0) ia2 = i; }
        else if (s == 2 * N_EDGES    && iei < 0) iei = i;
    }
    const float* x   = (const float*)d_in[ix];
    const float* W   = (const float*)d_in[iw];
    const float* as_ = (const float*)d_in[ia1];
    const float* ad_ = (const float*)d_in[ia2];
    const void*  ei  = d_in[iei];
    float*       out = (float*)d_out;

    k_detect<<<1, 256>>>((const unsigned*)ei);
    k_zero_deg<<<(N_NODES + 255) / 256, 256>>>();
    k_convert_hist<<<(N_EDGES + 255) / 256, 256>>>(ei);
    k_scan1<<<NBLK_SCAN, SCAN_BS>>>();
    k_scan2<<<1, 32>>>();
    k_scan3<<<(N_NODES + 255) / 256, 256>>>();
    k_gemm<<<(N_NODES + BM - 1) / BM, 256>>>(x, W, as_, ad_);
    k_reorder<<<(N_EDGES + 255) / 256, 256>>>();
    k_csr_agg<<<(N_NODES * 32 + 255) / 256, 256>>>(out);
}

// round 5
// speedup vs baseline: 2.9524x; 1.3360x over previous
#include <cuda_runtime.h>

#define N_NODES 100000
#define N_EDGES 1600000
#define C_IN    128
#define HEADS   4
#define HEAD_D  32
#define C_OUT   128
#define SCAN_BS 512
#define NBLK_SCAN ((N_NODES + SCAN_BS - 1) / SCAN_BS)   // 196

// ---- scratch ----
__device__ float g_xw[(size_t)N_NODES * C_OUT];      // 51.2 MB
__device__ float g_asrc[N_NODES * HEADS];
__device__ float g_adst[N_NODES * HEADS];
__device__ int   g_scol[N_EDGES];                    // cols grouped by row
__device__ int   g_deg[N_NODES];
__device__ int   g_rptr[N_NODES];
__device__ int   g_wp[N_NODES];
__device__ int   g_bsum[NBLK_SCAN];
__device__ int   g_is64;

// ---- detect int32 vs int64 edge_index ----
__global__ void k_detect(const unsigned* __restrict__ w) {
    __shared__ int nz;
    if (threadIdx.x == 0) nz = 0;
    __syncthreads();
    int bad = 0;
    for (int i = threadIdx.x; i < 2048; i += blockDim.x)
        if (w[2 * i + 1] != 0u) bad = 1;
    if (bad) atomicOr(&nz, 1);
    __syncthreads();
    if (threadIdx.x == 0) g_is64 = (nz == 0);
}

__global__ void k_zero_deg() {
    int i = blockIdx.x * blockDim.x + threadIdx.x;
    if (i < N_NODES) g_deg[i] = 0;
}

__device__ __forceinline__ int load_idx(const void* p, int i) {
    return g_is64 ? (int)((const long long*)p)[i] : ((const int*)p)[i];
}

// ---- row histogram straight from the raw index buffer ----
__global__ void k_hist(const void* __restrict__ ei_raw) {
    int e = blockIdx.x * blockDim.x + threadIdx.x;
    if (e >= N_EDGES) return;
    atomicAdd(&g_deg[load_idx(ei_raw, e)], 1);
}

// ---- exclusive scan of g_deg -> g_rptr (3 kernels) ----
__global__ void __launch_bounds__(SCAN_BS) k_scan1() {
    int i = blockIdx.x * SCAN_BS + threadIdx.x;
    int v = (i < N_NODES) ? g_deg[i] : 0;
    int lane = threadIdx.x & 31, wid = threadIdx.x >> 5;
    int inc = v;
    #pragma unroll
    for (int o = 1; o < 32; o <<= 1) {
        int t = __shfl_up_sync(0xFFFFFFFFu, inc, o);
        if (lane >= o) inc += t;
    }
    __shared__ int wsum[16];
    if (lane == 31) wsum[wid] = inc;
    __syncthreads();
    if (wid == 0 && lane < 16) {
        int s = wsum[lane];
        #pragma unroll
        for (int o = 1; o < 16; o <<= 1) {
            int t = __shfl_up_sync(0xFFFFu, s, o);
            if (lane >= o) s += t;
        }
        wsum[lane] = s;
    }
    __syncthreads();
    int warpoff = (wid == 0) ? 0 : wsum[wid - 1];
    if (i < N_NODES) g_rptr[i] = warpoff + inc - v;
    if (threadIdx.x == SCAN_BS - 1) g_bsum[blockIdx.x] = warpoff + inc;
}
__global__ void k_scan2() {   // parallel scan over NBLK_SCAN (<=256) block sums
    int t = threadIdx.x;
    int v = (t < NBLK_SCAN) ? g_bsum[t] : 0;
    int lane = t & 31, wid = t >> 5;
    int inc = v;
    #pragma unroll
    for (int o = 1; o < 32; o <<= 1) {
        int u = __shfl_up_sync(0xFFFFFFFFu, inc, o);
        if (lane >= o) inc += u;
    }
    __shared__ int ws2[8];
    if (lane == 31) ws2[wid] = inc;
    __syncthreads();
    if (wid == 0 && lane < 8) {
        int s = ws2[lane];
        #pragma unroll
        for (int o = 1; o < 8; o <<= 1) {
            int u = __shfl_up_sync(0xFFu, s, o);
            if (lane >= o) s += u;
        }
        ws2[lane] = s;
    }
    __syncthreads();
    int off = wid ? ws2[wid - 1] : 0;
    if (t < NBLK_SCAN) g_bsum[t] = off + inc - v;   // exclusive
}
__global__ void k_scan3() {
    int i = blockIdx.x * blockDim.x + threadIdx.x;
    if (i >= N_NODES) return;
    int v = g_rptr[i] + g_bsum[i >> 9];
    g_rptr[i] = v;
    g_wp[i]   = v;
}

// ---- group cols by row (reads raw index buffer twice, no staging) ----
__global__ void k_reorder(const void* __restrict__ ei_raw) {
    int e = blockIdx.x * blockDim.x + threadIdx.x;
    if (e >= N_EDGES) return;
    int r = load_idx(ei_raw, e);
    int c = load_idx(ei_raw, N_EDGES + e);
    int slot = atomicAdd(&g_wp[r], 1);
    g_scol[slot] = c;
}

// ==== TF32 tensor-core GEMM: xw = x @ W, fused attention logits ====
#define GBM 128
#define GBK 32

__device__ __forceinline__ unsigned f2tf32(float f) {
    unsigned r;
    asm("cvt.rna.tf32.f32 %0, %1;" : "=r"(r) : "f"(f));
    return r;
}
__device__ __forceinline__ void mma_tf32(float* d, const unsigned* a, const unsigned* b) {
    asm volatile("mma.sync.aligned.m16n8k8.row.col.f32.tf32.tf32.f32 "
                 "{%0,%1,%2,%3}, {%4,%5,%6,%7}, {%8,%9}, {%0,%1,%2,%3};"
                 : "+f"(d[0]), "+f"(d[1]), "+f"(d[2]), "+f"(d[3])
                 : "r"(a[0]), "r"(a[1]), "r"(a[2]), "r"(a[3]),
                   "r"(b[0]), "r"(b[1]));
}

__global__ void __launch_bounds__(256) k_gemm_tc(
    const float* __restrict__ x, const float* __restrict__ W,
    const float* __restrict__ att_src, const float* __restrict__ att_dst)
{
    __shared__ unsigned xs[GBM][GBK + 4];     // row stride 36: conflict-free A frags
    __shared__ unsigned ws[GBK][C_OUT + 8];   // row stride 136: conflict-free B frags

    const int t      = threadIdx.x;
    const int lane   = t & 31;
    const int wid    = t >> 5;
    const int warp_m = wid & 3;               // 4 M-groups of 32 rows
    const int warp_n = wid >> 2;              // 2 N-groups of 64 cols
    const int gq     = lane >> 2;             // groupID
    const int tig    = lane & 3;              // threadID_in_group
    const int row0   = blockIdx.x * GBM;

    float acc[2][8][4];
    #pragma unroll
    for (int mt = 0; mt < 2; ++mt)
        #pragma unroll
        for (int nt = 0; nt < 8; ++nt)
            #pragma unroll
            for (int q = 0; q < 4; ++q) acc[mt][nt][q] = 0.f;

    for (int kt = 0; kt < C_IN / GBK; ++kt) {
        // stage loads in registers, then sync, then fill smem
        float4 xv[4], wv[4];
        #pragma unroll
        for (int p = 0; p < 4; ++p) {
            int idx = t + p * 256;
            int r   = idx >> 3;
            int cq  = (idx & 7) * 4;
            int grow = min(row0 + r, N_NODES - 1);
            xv[p] = *reinterpret_cast<const float4*>(x + (size_t)grow * C_IN + kt * GBK + cq);
            int rw  = idx >> 5;
            int cw  = (idx & 31) * 4;
            wv[p] = *reinterpret_cast<const float4*>(W + (size_t)(kt * GBK + rw) * C_OUT + cw);
        }
        __syncthreads();
        #pragma unroll
        for (int p = 0; p < 4; ++p) {
            int idx = t + p * 256;
            int r   = idx >> 3;
            int cq  = (idx & 7) * 4;
            xs[r][cq + 0] = f2tf32(xv[p].x);
            xs[r][cq + 1] = f2tf32(xv[p].y);
            xs[r][cq + 2] = f2tf32(xv[p].z);
            xs[r][cq + 3] = f2tf32(xv[p].w);
            int rw  = idx >> 5;
            int cw  = (idx & 31) * 4;
            ws[rw][cw + 0] = f2tf32(wv[p].x);
            ws[rw][cw + 1] = f2tf32(wv[p].y);
            ws[rw][cw + 2] = f2tf32(wv[p].z);
            ws[rw][cw + 3] = f2tf32(wv[p].w);
        }
        __syncthreads();

        #pragma unroll
        for (int ks = 0; ks < GBK / 8; ++ks) {
            int k0 = ks * 8;
            unsigned a[2][4], b[8][2];
            #pragma unroll
            for (int mt = 0; mt < 2; ++mt) {
                int rb = warp_m * 32 + mt * 16;
                a[mt][0] = xs[rb + gq][k0 + tig];
                a[mt][1] = xs[rb + gq + 8][k0 + tig];
                a[mt][2] = xs[rb + gq][k0 + tig + 4];
                a[mt][3] = xs[rb + gq + 8][k0 + tig + 4];
            }
            #pragma unroll
            for (int nt = 0; nt < 8; ++nt) {
                int n0 = warp_n * 64 + nt * 8;
                b[nt][0] = ws[k0 + tig][n0 + gq];
                b[nt][1] = ws[k0 + tig + 4][n0 + gq];
            }
            #pragma unroll
            for (int mt = 0; mt < 2; ++mt)
                #pragma unroll
                for (int nt = 0; nt < 8; ++nt)
                    mma_tf32(acc[mt][nt], a[mt], b[nt]);
        }
    }

    // write xw: c0/c1 -> (row gq, cols 2tig,2tig+1); c2/c3 -> row gq+8
    #pragma unroll
    for (int mt = 0; mt < 2; ++mt)
        #pragma unroll
        for (int half = 0; half < 2; ++half) {
            int row = row0 + warp_m * 32 + mt * 16 + gq + half * 8;
            if (row < N_NODES) {
                #pragma unroll
                for (int nt = 0; nt < 8; ++nt) {
                    int col = warp_n * 64 + nt * 8 + tig * 2;
                    *reinterpret_cast<float2*>(g_xw + (size_t)row * C_OUT + col) =
                        make_float2(acc[mt][nt][half * 2 + 0], acc[mt][nt][half * 2 + 1]);
                }
            }
        }

    // attention logits from accumulator fragments.
    // att_src/att_dst are [H][32] contiguous => flat index == global column.
    float ats[2][8], atd[2][8];
    #pragma unroll
    for (int hh = 0; hh < 2; ++hh)
        #pragma unroll
        for (int j = 0; j < 4; ++j)
            #pragma unroll
            for (int d = 0; d < 2; ++d) {
                int col = warp_n * 64 + (hh * 4 + j) * 8 + tig * 2 + d;
                ats[hh][j * 2 + d] = att_src[col];
                atd[hh][j * 2 + d] = att_dst[col];
            }
    #pragma unroll
    for (int mt = 0; mt < 2; ++mt)
        #pragma unroll
        for (int half = 0; half < 2; ++half) {
            int row = row0 + warp_m * 32 + mt * 16 + gq + half * 8;
            float vs[2] = {0.f, 0.f}, vd[2] = {0.f, 0.f};
            #pragma unroll
            for (int hh = 0; hh < 2; ++hh)
                #pragma unroll
                for (int j = 0; j < 4; ++j)
                    #pragma unroll
                    for (int d = 0; d < 2; ++d) {
                        float av = acc[mt][hh * 4 + j][half * 2 + d];
                        vs[hh] += av * ats[hh][j * 2 + d];
                        vd[hh] += av * atd[hh][j * 2 + d];
                    }
            #pragma unroll
            for (int hh = 0; hh < 2; ++hh) {
                vs[hh] += __shfl_down_sync(0xFFFFFFFFu, vs[hh], 2);
                vs[hh] += __shfl_down_sync(0xFFFFFFFFu, vs[hh], 1);
                vd[hh] += __shfl_down_sync(0xFFFFFFFFu, vd[hh], 2);
                vd[hh] += __shfl_down_sync(0xFFFFFFFFu, vd[hh], 1);
            }
            if (tig == 0 && row < N_NODES) {
                #pragma unroll
                for (int hh = 0; hh < 2; ++hh) {
                    int h = warp_n * 2 + hh;
                    g_asrc[row * HEADS + h] = vs[hh];
                    g_adst[row * HEADS + h] = vd[hh];
                }
            }
        }
}

// ---- CSR aggregation: one warp per node ----
__global__ void __launch_bounds__(256) k_csr_agg(float* __restrict__ out) {
    int n = (blockIdx.x * blockDim.x + threadIdx.x) >> 5;
    if (n >= N_NODES) return;
    int lane = threadIdx.x & 31;
    int h    = lane >> 3;

    int start = g_rptr[n];
    int deg   = g_deg[n];
    float asrc_h = g_asrc[n * HEADS + h];

    float4 acc = make_float4(0.f, 0.f, 0.f, 0.f);
    float  asum = 0.f;

    int c_next = (deg > 0) ? g_scol[start] : 0;
    for (int j = 0; j < deg; ++j) {
        int c = c_next;
        if (j + 1 < deg) c_next = g_scol[start + j + 1];
        float lr = asrc_h + g_adst[c * HEADS + h];
        lr = lr > 0.f ? lr : 0.2f * lr;
        float ex = __expf(lr);
        float4 v = *reinterpret_cast<const float4*>(g_xw + (size_t)c * C_OUT + lane * 4);
        acc.x += ex * v.x;
        acc.y += ex * v.y;
        acc.z += ex * v.z;
        acc.w += ex * v.w;
        asum  += ex;
    }
    float inv = 1.f / (asum + 1e-16f);
    acc.x *= inv; acc.y *= inv; acc.z *= inv; acc.w *= inv;
    *reinterpret_cast<float4*>(out + (size_t)n * C_OUT + lane * 4) = acc;
}

extern "C" void kernel_launch(void* const* d_in, const int* in_sizes, int n_in,
                              void* d_out, int out_size)
{
    int ix = -1, iw = -1, ia1 = -1, ia2 = -1, iei = -1;
    for (int i = 0; i < n_in; ++i) {
        int s = in_sizes[i];
        if      (s == N_NODES * C_IN && ix < 0)  ix = i;
        else if (s == C_IN * C_OUT   && iw < 0)  iw = i;
        else if (s == HEADS * HEAD_D) { if (ia1 < 0) ia1 = i; else if (ia2 < 0) ia2 = i; }
        else if (s == 2 * N_EDGES    && iei < 0) iei = i;
    }
    const float* x   = (const float*)d_in[ix];
    const float* W   = (const float*)d_in[iw];
    const float* as_ = (const float*)d_in[ia1];
    const float* ad_ = (const float*)d_in[ia2];
    const void*  ei  = d_in[iei];
    float*       out = (float*)d_out;

    k_detect<<<1, 256>>>((const unsigned*)ei);
    k_zero_deg<<<(N_NODES + 255) / 256, 256>>>();
    k_hist<<<(N_EDGES + 255) / 256, 256>>>(ei);
    k_scan1<<<NBLK_SCAN, SCAN_BS>>>();
    k_scan2<<<1, 256>>>();
    k_scan3<<<(N_NODES + 255) / 256, 256>>>();
    k_gemm_tc<<<(N_NODES + GBM - 1) / GBM, 256>>>(x, W, as_, ad_);
    k_reorder<<<(N_EDGES + 255) / 256, 256>>>(ei);
    k_csr_agg<<<(N_NODES * 32 + 255) / 256, 256>>>(out);
}

// round 6
// speedup vs baseline: 3.0002x; 1.0162x over previous
#include <cuda_runtime.h>
#include <cuda_fp16.h>

#define N_NODES 100000
#define N_EDGES 1600000
#define C_IN    128
#define HEADS   4
#define HEAD_D  32
#define C_OUT   128
#define SCAN_BS 512
#define NBLK_SCAN ((N_NODES + SCAN_BS - 1) / SCAN_BS)   // 196

// ---- scratch ----
__device__ __half2 g_xw2[(size_t)N_NODES * (C_OUT / 2)];   // 25.6 MB, fp16
__device__ float   g_asrc[N_NODES * HEADS];
__device__ float   g_adst[N_NODES * HEADS];
__device__ int     g_scol[N_EDGES];                        // cols grouped by row
__device__ int     g_deg[N_NODES];
__device__ int     g_rptr[N_NODES];
__device__ int     g_wp[N_NODES];
__device__ int     g_bsum[NBLK_SCAN];
__device__ int     g_is64;

// ---- detect int32 vs int64 edge_index ----
__global__ void k_detect(const unsigned* __restrict__ w) {
    __shared__ int nz;
    if (threadIdx.x == 0) nz = 0;
    __syncthreads();
    int bad = 0;
    for (int i = threadIdx.x; i < 2048; i += blockDim.x)
        if (w[2 * i + 1] != 0u) bad = 1;
    if (bad) atomicOr(&nz, 1);
    __syncthreads();
    if (threadIdx.x == 0) g_is64 = (nz == 0);
}

__global__ void k_zero_deg() {
    int i = blockIdx.x * blockDim.x + threadIdx.x;
    if (i < N_NODES) g_deg[i] = 0;
}

__device__ __forceinline__ int load_idx(const void* p, int i) {
    return g_is64 ? (int)((const long long*)p)[i] : ((const int*)p)[i];
}

// ---- row histogram straight from the raw index buffer ----
__global__ void k_hist(const void* __restrict__ ei_raw) {
    int e = blockIdx.x * blockDim.x + threadIdx.x;
    if (e >= N_EDGES) return;
    atomicAdd(&g_deg[load_idx(ei_raw, e)], 1);
}

// ---- exclusive scan of g_deg -> g_rptr (3 kernels) ----
__global__ void __launch_bounds__(SCAN_BS) k_scan1() {
    int i = blockIdx.x * SCAN_BS + threadIdx.x;
    int v = (i < N_NODES) ? g_deg[i] : 0;
    int lane = threadIdx.x & 31, wid = threadIdx.x >> 5;
    int inc = v;
    #pragma unroll
    for (int o = 1; o < 32; o <<= 1) {
        int t = __shfl_up_sync(0xFFFFFFFFu, inc, o);
        if (lane >= o) inc += t;
    }
    __shared__ int wsum[16];
    if (lane == 31) wsum[wid] = inc;
    __syncthreads();
    if (wid == 0 && lane < 16) {
        int s = wsum[lane];
        #pragma unroll
        for (int o = 1; o < 16; o <<= 1) {
            int t = __shfl_up_sync(0xFFFFu, s, o);
            if (lane >= o) s += t;
        }
        wsum[lane] = s;
    }
    __syncthreads();
    int warpoff = (wid == 0) ? 0 : wsum[wid - 1];
    if (i < N_NODES) g_rptr[i] = warpoff + inc - v;
    if (threadIdx.x == SCAN_BS - 1) g_bsum[blockIdx.x] = warpoff + inc;
}
__global__ void k_scan2() {   // parallel scan over NBLK_SCAN (<=256) block sums
    int t = threadIdx.x;
    int v = (t < NBLK_SCAN) ? g_bsum[t] : 0;
    int lane = t & 31, wid = t >> 5;
    int inc = v;
    #pragma unroll
    for (int o = 1; o < 32; o <<= 1) {
        int u = __shfl_up_sync(0xFFFFFFFFu, inc, o);
        if (lane >= o) inc += u;
    }
    __shared__ int ws2[8];
    if (lane == 31) ws2[wid] = inc;
    __syncthreads();
    if (wid == 0 && lane < 8) {
        int s = ws2[lane];
        #pragma unroll
        for (int o = 1; o < 8; o <<= 1) {
            int u = __shfl_up_sync(0xFFu, s, o);
            if (lane >= o) s += u;
        }
        ws2[lane] = s;
    }
    __syncthreads();
    int off = wid ? ws2[wid - 1] : 0;
    if (t < NBLK_SCAN) g_bsum[t] = off + inc - v;   // exclusive
}
__global__ void k_scan3() {
    int i = blockIdx.x * blockDim.x + threadIdx.x;
    if (i >= N_NODES) return;
    int v = g_rptr[i] + g_bsum[i >> 9];
    g_rptr[i] = v;
    g_wp[i]   = v;
}

// ---- group cols by row ----
__global__ void k_reorder(const void* __restrict__ ei_raw) {
    int e = blockIdx.x * blockDim.x + threadIdx.x;
    if (e >= N_EDGES) return;
    int r = load_idx(ei_raw, e);
    int c = load_idx(ei_raw, N_EDGES + e);
    int slot = atomicAdd(&g_wp[r], 1);
    g_scol[slot] = c;
}

// ==== TF32 tensor-core GEMM: xw = x @ W, fused attention logits ====
#define GBM 128
#define GBK 32

__device__ __forceinline__ unsigned f2tf32(float f) {
    unsigned r;
    asm("cvt.rna.tf32.f32 %0, %1;" : "=r"(r) : "f"(f));
    return r;
}
__device__ __forceinline__ void mma_tf32(float* d, const unsigned* a, const unsigned* b) {
    asm volatile("mma.sync.aligned.m16n8k8.row.col.f32.tf32.tf32.f32 "
                 "{%0,%1,%2,%3}, {%4,%5,%6,%7}, {%8,%9}, {%0,%1,%2,%3};"
                 : "+f"(d[0]), "+f"(d[1]), "+f"(d[2]), "+f"(d[3])
                 : "r"(a[0]), "r"(a[1]), "r"(a[2]), "r"(a[3]),
                   "r"(b[0]), "r"(b[1]));
}

__global__ void __launch_bounds__(256) k_gemm_tc(
    const float* __restrict__ x, const float* __restrict__ W,
    const float* __restrict__ att_src, const float* __restrict__ att_dst)
{
    __shared__ unsigned xs[GBM][GBK + 4];
    __shared__ unsigned ws[GBK][C_OUT + 8];

    const int t      = threadIdx.x;
    const int lane   = t & 31;
    const int wid    = t >> 5;
    const int warp_m = wid & 3;
    const int warp_n = wid >> 2;
    const int gq     = lane >> 2;
    const int tig    = lane & 3;
    const int row0   = blockIdx.x * GBM;

    float acc[2][8][4];
    #pragma unroll
    for (int mt = 0; mt < 2; ++mt)
        #pragma unroll
        for (int nt = 0; nt < 8; ++nt)
            #pragma unroll
            for (int q = 0; q < 4; ++q) acc[mt][nt][q] = 0.f;

    for (int kt = 0; kt < C_IN / GBK; ++kt) {
        float4 xv[4], wv[4];
        #pragma unroll
        for (int p = 0; p < 4; ++p) {
            int idx = t + p * 256;
            int r   = idx >> 3;
            int cq  = (idx & 7) * 4;
            int grow = min(row0 + r, N_NODES - 1);
            xv[p] = *reinterpret_cast<const float4*>(x + (size_t)grow * C_IN + kt * GBK + cq);
            int rw  = idx >> 5;
            int cw  = (idx & 31) * 4;
            wv[p] = *reinterpret_cast<const float4*>(W + (size_t)(kt * GBK + rw) * C_OUT + cw);
        }
        __syncthreads();
        #pragma unroll
        for (int p = 0; p < 4; ++p) {
            int idx = t + p * 256;
            int r   = idx >> 3;
            int cq  = (idx & 7) * 4;
            xs[r][cq + 0] = f2tf32(xv[p].x);
            xs[r][cq + 1] = f2tf32(xv[p].y);
            xs[r][cq + 2] = f2tf32(xv[p].z);
            xs[r][cq + 3] = f2tf32(xv[p].w);
            int rw  = idx >> 5;
            int cw  = (idx & 31) * 4;
            ws[rw][cw + 0] = f2tf32(wv[p].x);
            ws[rw][cw + 1] = f2tf32(wv[p].y);
            ws[rw][cw + 2] = f2tf32(wv[p].z);
            ws[rw][cw + 3] = f2tf32(wv[p].w);
        }
        __syncthreads();

        #pragma unroll
        for (int ks = 0; ks < GBK / 8; ++ks) {
            int k0 = ks * 8;
            unsigned a[2][4], b[8][2];
            #pragma unroll
            for (int mt = 0; mt < 2; ++mt) {
                int rb = warp_m * 32 + mt * 16;
                a[mt][0] = xs[rb + gq][k0 + tig];
                a[mt][1] = xs[rb + gq + 8][k0 + tig];
                a[mt][2] = xs[rb + gq][k0 + tig + 4];
                a[mt][3] = xs[rb + gq + 8][k0 + tig + 4];
            }
            #pragma unroll
            for (int nt = 0; nt < 8; ++nt) {
                int n0 = warp_n * 64 + nt * 8;
                b[nt][0] = ws[k0 + tig][n0 + gq];
                b[nt][1] = ws[k0 + tig + 4][n0 + gq];
            }
            #pragma unroll
            for (int mt = 0; mt < 2; ++mt)
                #pragma unroll
                for (int nt = 0; nt < 8; ++nt)
                    mma_tf32(acc[mt][nt], a[mt], b[nt]);
        }
    }

    // write xw as fp16 (half2 per 2 adjacent cols)
    #pragma unroll
    for (int mt = 0; mt < 2; ++mt)
        #pragma unroll
        for (int half = 0; half < 2; ++half) {
            int row = row0 + warp_m * 32 + mt * 16 + gq + half * 8;
            if (row < N_NODES) {
                #pragma unroll
                for (int nt = 0; nt < 8; ++nt) {
                    int c2 = warp_n * 32 + nt * 4 + tig;   // half2 index (col/2)
                    g_xw2[(size_t)row * (C_OUT / 2) + c2] =
                        __floats2half2_rn(acc[mt][nt][half * 2 + 0],
                                          acc[mt][nt][half * 2 + 1]);
                }
            }
        }

    // attention logits from fp32 accumulator fragments
    float ats[2][8], atd[2][8];
    #pragma unroll
    for (int hh = 0; hh < 2; ++hh)
        #pragma unroll
        for (int j = 0; j < 4; ++j)
            #pragma unroll
            for (int d = 0; d < 2; ++d) {
                int col = warp_n * 64 + (hh * 4 + j) * 8 + tig * 2 + d;
                ats[hh][j * 2 + d] = att_src[col];
                atd[hh][j * 2 + d] = att_dst[col];
            }
    #pragma unroll
    for (int mt = 0; mt < 2; ++mt)
        #pragma unroll
        for (int half = 0; half < 2; ++half) {
            int row = row0 + warp_m * 32 + mt * 16 + gq + half * 8;
            float vs[2] = {0.f, 0.f}, vd[2] = {0.f, 0.f};
            #pragma unroll
            for (int hh = 0; hh < 2; ++hh)
                #pragma unroll
                for (int j = 0; j < 4; ++j)
                    #pragma unroll
                    for (int d = 0; d < 2; ++d) {
                        float av = acc[mt][hh * 4 + j][half * 2 + d];
                        vs[hh] += av * ats[hh][j * 2 + d];
                        vd[hh] += av * atd[hh][j * 2 + d];
                    }
            #pragma unroll
            for (int hh = 0; hh < 2; ++hh) {
                vs[hh] += __shfl_down_sync(0xFFFFFFFFu, vs[hh], 2);
                vs[hh] += __shfl_down_sync(0xFFFFFFFFu, vs[hh], 1);
                vd[hh] += __shfl_down_sync(0xFFFFFFFFu, vd[hh], 2);
                vd[hh] += __shfl_down_sync(0xFFFFFFFFu, vd[hh], 1);
            }
            if (tig == 0 && row < N_NODES) {
                #pragma unroll
                for (int hh = 0; hh < 2; ++hh) {
                    int h = warp_n * 2 + hh;
                    g_asrc[row * HEADS + h] = vs[hh];
                    g_adst[row * HEADS + h] = vd[hh];
                }
            }
        }
}

// ---- CSR aggregation: one warp per node, fp16 gathers, fp32 math ----
__global__ void __launch_bounds__(256) k_csr_agg(float* __restrict__ out) {
    int n = (blockIdx.x * blockDim.x + threadIdx.x) >> 5;
    if (n >= N_NODES) return;
    int lane = threadIdx.x & 31;
    int h    = lane >> 3;

    int start = g_rptr[n];
    int deg   = g_deg[n];
    float asrc_h = g_asrc[n * HEADS + h];

    float4 acc = make_float4(0.f, 0.f, 0.f, 0.f);
    float  asum = 0.f;

    int c_next = (deg > 0) ? g_scol[start] : 0;
    for (int j = 0; j < deg; ++j) {
        int c = c_next;
        if (j + 1 < deg) c_next = g_scol[start + j + 1];
        float lr = asrc_h + g_adst[c * HEADS + h];
        lr = lr > 0.f ? lr : 0.2f * lr;
        float ex = __expf(lr);
        uint2 raw = *reinterpret_cast<const uint2*>(
            g_xw2 + (size_t)c * (C_OUT / 2) + lane * 2);
        float2 f0 = __half22float2(*reinterpret_cast<__half2*>(&raw.x));
        float2 f1 = __half22float2(*reinterpret_cast<__half2*>(&raw.y));
        acc.x += ex * f0.x;
        acc.y += ex * f0.y;
        acc.z += ex * f1.x;
        acc.w += ex * f1.y;
        asum  += ex;
    }
    float inv = 1.f / (asum + 1e-16f);
    acc.x *= inv; acc.y *= inv; acc.z *= inv; acc.w *= inv;
    *reinterpret_cast<float4*>(out + (size_t)n * C_OUT + lane * 4) = acc;
}

extern "C" void kernel_launch(void* const* d_in, const int* in_sizes, int n_in,
                              void* d_out, int out_size)
{
    int ix = -1, iw = -1, ia1 = -1, ia2 = -1, iei = -1;
    for (int i = 0; i < n_in; ++i) {
        int s = in_sizes[i];
        if      (s == N_NODES * C_IN && ix < 0)  ix = i;
        else if (s == C_IN * C_OUT   && iw < 0)  iw = i;
        else if (s == HEADS * HEAD_D) { if (ia1 < 0) ia1 = i; else if (ia2 < 0) ia2 = i; }
        else if (s == 2 * N_EDGES    && iei < 0) iei = i;
    }
    const float* x   = (const float*)d_in[ix];
    const float* W   = (const float*)d_in[iw];
    const float* as_ = (const float*)d_in[ia1];
    const float* ad_ = (const float*)d_in[ia2];
    const void*  ei  = d_in[iei];
    float*       out = (float*)d_out;

    k_detect<<<1, 256>>>((const unsigned*)ei);
    k_zero_deg<<<(N_NODES + 255) / 256, 256>>>();
    k_hist<<<(N_EDGES + 255) / 256, 256>>>(ei);
    k_scan1<<<NBLK_SCAN, SCAN_BS>>>();
    k_scan2<<<1, 256>>>();
    k_scan3<<<(N_NODES + 255) / 256, 256>>>();
    k_gemm_tc<<<(N_NODES + GBM - 1) / GBM, 256>>>(x, W, as_, ad_);
    k_reorder<<<(N_EDGES + 255) / 256, 256>>>(ei);
    k_csr_agg<<<(N_NODES * 32 + 255) / 256, 256>>>(out);
}

// round 7
// speedup vs baseline: 3.3609x; 1.1202x over previous
#include <cuda_runtime.h>
#include <cuda_fp16.h>

#define N_NODES 100000
#define N_EDGES 1600000
#define C_IN    128
#define HEADS   4
#define HEAD_D  32
#define C_OUT   128
#define SCAN_BS 512
#define NBLK_SCAN ((N_NODES + SCAN_BS - 1) / SCAN_BS)   // 196

// ---- scratch ----
__device__ __half2 g_xw2[(size_t)N_NODES * (C_OUT / 2)];   // 25.6 MB, fp16
__device__ float   g_asrc[N_NODES * HEADS];
__device__ float   g_adst[N_NODES * HEADS];
__device__ int     g_scol[N_EDGES];
__device__ int     g_deg[N_NODES];
__device__ int     g_rptr[N_NODES];
__device__ int     g_wp[N_NODES];
__device__ int     g_bsum[NBLK_SCAN];
__device__ int     g_is64;

// ---- detect dtype (block 0) + zero degree histogram (all blocks) ----
__global__ void k_prep(const unsigned* __restrict__ w) {
    int i = blockIdx.x * blockDim.x + threadIdx.x;
    if (i < N_NODES) g_deg[i] = 0;
    if (blockIdx.x == 0) {
        __shared__ int nz;
        if (threadIdx.x == 0) nz = 0;
        __syncthreads();
        int bad = 0;
        for (int k = threadIdx.x; k < 2048; k += blockDim.x)
            if (w[2 * k + 1] != 0u) bad = 1;
        if (bad) atomicOr(&nz, 1);
        __syncthreads();
        if (threadIdx.x == 0) g_is64 = (nz == 0);
    }
}

// load 4 consecutive indices starting at base (base % 4 == 0)
__device__ __forceinline__ void load_idx4(const void* p, int base, int* c) {
    if (g_is64) {
        longlong2 a = ((const longlong2*)p)[base >> 1];
        longlong2 b = ((const longlong2*)p)[(base >> 1) + 1];
        c[0] = (int)a.x; c[1] = (int)a.y; c[2] = (int)b.x; c[3] = (int)b.y;
    } else {
        int4 v = ((const int4*)p)[base >> 2];
        c[0] = v.x; c[1] = v.y; c[2] = v.z; c[3] = v.w;
    }
}

// ---- row histogram: 4 edges per thread ----
__global__ void k_hist(const void* __restrict__ ei_raw) {
    int base = (blockIdx.x * blockDim.x + threadIdx.x) * 4;
    if (base >= N_EDGES) return;
    int r[4];
    load_idx4(ei_raw, base, r);
    #pragma unroll
    for (int k = 0; k < 4; ++k) atomicAdd(&g_deg[r[k]], 1);
}

// ---- exclusive scan of g_deg -> g_rptr ----
__global__ void __launch_bounds__(SCAN_BS) k_scan1() {
    int i = blockIdx.x * SCAN_BS + threadIdx.x;
    int v = (i < N_NODES) ? g_deg[i] : 0;
    int lane = threadIdx.x & 31, wid = threadIdx.x >> 5;
    int inc = v;
    #pragma unroll
    for (int o = 1; o < 32; o <<= 1) {
        int t = __shfl_up_sync(0xFFFFFFFFu, inc, o);
        if (lane >= o) inc += t;
    }
    __shared__ int wsum[16];
    if (lane == 31) wsum[wid] = inc;
    __syncthreads();
    if (wid == 0 && lane < 16) {
        int s = wsum[lane];
        #pragma unroll
        for (int o = 1; o < 16; o <<= 1) {
            int t = __shfl_up_sync(0xFFFFu, s, o);
            if (lane >= o) s += t;
        }
        wsum[lane] = s;
    }
    __syncthreads();
    int warpoff = (wid == 0) ? 0 : wsum[wid - 1];
    if (i < N_NODES) g_rptr[i] = warpoff + inc - v;
    if (threadIdx.x == SCAN_BS - 1) g_bsum[blockIdx.x] = warpoff + inc;
}
__global__ void k_scan2() {
    int t = threadIdx.x;
    int v = (t < NBLK_SCAN) ? g_bsum[t] : 0;
    int lane = t & 31, wid = t >> 5;
    int inc = v;
    #pragma unroll
    for (int o = 1; o < 32; o <<= 1) {
        int u = __shfl_up_sync(0xFFFFFFFFu, inc, o);
        if (lane >= o) inc += u;
    }
    __shared__ int ws2[8];
    if (lane == 31) ws2[wid] = inc;
    __syncthreads();
    if (wid == 0 && lane < 8) {
        int s = ws2[lane];
        #pragma unroll
        for (int o = 1; o < 8; o <<= 1) {
            int u = __shfl_up_sync(0xFFu, s, o);
            if (lane >= o) s += u;
        }
        ws2[lane] = s;
    }
    __syncthreads();
    int off = wid ? ws2[wid - 1] : 0;
    if (t < NBLK_SCAN) g_bsum[t] = off + inc - v;
}
__global__ void k_scan3() {
    int i = blockIdx.x * blockDim.x + threadIdx.x;
    if (i >= N_NODES) return;
    int v = g_rptr[i] + g_bsum[i >> 9];
    g_rptr[i] = v;
    g_wp[i]   = v;
}

// ---- group cols by row: 4 edges per thread ----
__global__ void k_reorder(const void* __restrict__ ei_raw) {
    int base = (blockIdx.x * blockDim.x + threadIdx.x) * 4;
    if (base >= N_EDGES) return;
    int r[4], c[4], slot[4];
    load_idx4(ei_raw, base, r);
    load_idx4(ei_raw, N_EDGES + base, c);
    #pragma unroll
    for (int k = 0; k < 4; ++k) slot[k] = atomicAdd(&g_wp[r[k]], 1);
    #pragma unroll
    for (int k = 0; k < 4; ++k) g_scol[slot[k]] = c[k];
}

// ==== TF32 tensor-core GEMM: xw = x @ W, fused attention logits ====
#define GBM 128
#define GBK 32

__device__ __forceinline__ unsigned f2tf32(float f) {
    unsigned r;
    asm("cvt.rna.tf32.f32 %0, %1;" : "=r"(r) : "f"(f));
    return r;
}
__device__ __forceinline__ void mma_tf32(float* d, const unsigned* a, const unsigned* b) {
    asm volatile("mma.sync.aligned.m16n8k8.row.col.f32.tf32.tf32.f32 "
                 "{%0,%1,%2,%3}, {%4,%5,%6,%7}, {%8,%9}, {%0,%1,%2,%3};"
                 : "+f"(d[0]), "+f"(d[1]), "+f"(d[2]), "+f"(d[3])
                 : "r"(a[0]), "r"(a[1]), "r"(a[2]), "r"(a[3]),
                   "r"(b[0]), "r"(b[1]));
}

__global__ void __launch_bounds__(256) k_gemm_tc(
    const float* __restrict__ x, const float* __restrict__ W,
    const float* __restrict__ att_src, const float* __restrict__ att_dst)
{
    __shared__ unsigned xs[GBM][GBK + 4];
    __shared__ unsigned ws[GBK][C_OUT + 8];

    const int t      = threadIdx.x;
    const int lane   = t & 31;
    const int wid    = t >> 5;
    const int warp_m = wid & 3;
    const int warp_n = wid >> 2;
    const int gq     = lane >> 2;
    const int tig    = lane & 3;
    const int row0   = blockIdx.x * GBM;

    float acc[2][8][4];
    #pragma unroll
    for (int mt = 0; mt < 2; ++mt)
        #pragma unroll
        for (int nt = 0; nt < 8; ++nt)
            #pragma unroll
            for (int q = 0; q < 4; ++q) acc[mt][nt][q] = 0.f;

    for (int kt = 0; kt < C_IN / GBK; ++kt) {
        float4 xv[4], wv[4];
        #pragma unroll
        for (int p = 0; p < 4; ++p) {
            int idx = t + p * 256;
            int r   = idx >> 3;
            int cq  = (idx & 7) * 4;
            int grow = min(row0 + r, N_NODES - 1);
            xv[p] = *reinterpret_cast<const float4*>(x + (size_t)grow * C_IN + kt * GBK + cq);
            int rw  = idx >> 5;
            int cw  = (idx & 31) * 4;
            wv[p] = *reinterpret_cast<const float4*>(W + (size_t)(kt * GBK + rw) * C_OUT + cw);
        }
        __syncthreads();
        #pragma unroll
        for (int p = 0; p < 4; ++p) {
            int idx = t + p * 256;
            int r   = idx >> 3;
            int cq  = (idx & 7) * 4;
            xs[r][cq + 0] = f2tf32(xv[p].x);
            xs[r][cq + 1] = f2tf32(xv[p].y);
            xs[r][cq + 2] = f2tf32(xv[p].z);
            xs[r][cq + 3] = f2tf32(xv[p].w);
            int rw  = idx >> 5;
            int cw  = (idx & 31) * 4;
            ws[rw][cw + 0] = f2tf32(wv[p].x);
            ws[rw][cw + 1] = f2tf32(wv[p].y);
            ws[rw][cw + 2] = f2tf32(wv[p].z);
            ws[rw][cw + 3] = f2tf32(wv[p].w);
        }
        __syncthreads();

        #pragma unroll
        for (int ks = 0; ks < GBK / 8; ++ks) {
            int k0 = ks * 8;
            unsigned a[2][4], b[8][2];
            #pragma unroll
            for (int mt = 0; mt < 2; ++mt) {
                int rb = warp_m * 32 + mt * 16;
                a[mt][0] = xs[rb + gq][k0 + tig];
                a[mt][1] = xs[rb + gq + 8][k0 + tig];
                a[mt][2] = xs[rb + gq][k0 + tig + 4];
                a[mt][3] = xs[rb + gq + 8][k0 + tig + 4];
            }
            #pragma unroll
            for (int nt = 0; nt < 8; ++nt) {
                int n0 = warp_n * 64 + nt * 8;
                b[nt][0] = ws[k0 + tig][n0 + gq];
                b[nt][1] = ws[k0 + tig + 4][n0 + gq];
            }
            #pragma unroll
            for (int mt = 0; mt < 2; ++mt)
                #pragma unroll
                for (int nt = 0; nt < 8; ++nt)
                    mma_tf32(acc[mt][nt], a[mt], b[nt]);
        }
    }

    #pragma unroll
    for (int mt = 0; mt < 2; ++mt)
        #pragma unroll
        for (int half = 0; half < 2; ++half) {
            int row = row0 + warp_m * 32 + mt * 16 + gq + half * 8;
            if (row < N_NODES) {
                #pragma unroll
                for (int nt = 0; nt < 8; ++nt) {
                    int c2 = warp_n * 32 + nt * 4 + tig;
                    g_xw2[(size_t)row * (C_OUT / 2) + c2] =
                        __floats2half2_rn(acc[mt][nt][half * 2 + 0],
                                          acc[mt][nt][half * 2 + 1]);
                }
            }
        }

    float ats[2][8], atd[2][8];
    #pragma unroll
    for (int hh = 0; hh < 2; ++hh)
        #pragma unroll
        for (int j = 0; j < 4; ++j)
            #pragma unroll
            for (int d = 0; d < 2; ++d) {
                int col = warp_n * 64 + (hh * 4 + j) * 8 + tig * 2 + d;
                ats[hh][j * 2 + d] = att_src[col];
                atd[hh][j * 2 + d] = att_dst[col];
            }
    #pragma unroll
    for (int mt = 0; mt < 2; ++mt)
        #pragma unroll
        for (int half = 0; half < 2; ++half) {
            int row = row0 + warp_m * 32 + mt * 16 + gq + half * 8;
            float vs[2] = {0.f, 0.f}, vd[2] = {0.f, 0.f};
            #pragma unroll
            for (int hh = 0; hh < 2; ++hh)
                #pragma unroll
                for (int j = 0; j < 4; ++j)
                    #pragma unroll
                    for (int d = 0; d < 2; ++d) {
                        float av = acc[mt][hh * 4 + j][half * 2 + d];
                        vs[hh] += av * ats[hh][j * 2 + d];
                        vd[hh] += av * atd[hh][j * 2 + d];
                    }
            #pragma unroll
            for (int hh = 0; hh < 2; ++hh) {
                vs[hh] += __shfl_down_sync(0xFFFFFFFFu, vs[hh], 2);
                vs[hh] += __shfl_down_sync(0xFFFFFFFFu, vs[hh], 1);
                vd[hh] += __shfl_down_sync(0xFFFFFFFFu, vd[hh], 2);
                vd[hh] += __shfl_down_sync(0xFFFFFFFFu, vd[hh], 1);
            }
            if (tig == 0 && row < N_NODES) {
                #pragma unroll
                for (int hh = 0; hh < 2; ++hh) {
                    int h = warp_n * 2 + hh;
                    g_asrc[row * HEADS + h] = vs[hh];
                    g_adst[row * HEADS + h] = vd[hh];
                }
            }
        }
}

// ---- CSR aggregation: one warp per node, 4-way unrolled for MLP ----
__global__ void __launch_bounds__(256) k_csr_agg(float* __restrict__ out) {
    int n = (blockIdx.x * blockDim.x + threadIdx.x) >> 5;
    if (n >= N_NODES) return;
    int lane = threadIdx.x & 31;
    int h    = lane >> 3;

    int start = g_rptr[n];
    int deg   = g_deg[n];
    float asrc_h = g_asrc[n * HEADS + h];

    float4 acc = make_float4(0.f, 0.f, 0.f, 0.f);
    float  asum = 0.f;
    const size_t loff = (size_t)lane * 2;

    int j = 0;
    for (; j + 4 <= deg; j += 4) {
        // batch all independent loads up front (MLP = 4 per level)
        int c0 = g_scol[start + j + 0];
        int c1 = g_scol[start + j + 1];
        int c2 = g_scol[start + j + 2];
        int c3 = g_scol[start + j + 3];
        float a0 = g_adst[c0 * HEADS + h];
        float a1 = g_adst[c1 * HEADS + h];
        float a2 = g_adst[c2 * HEADS + h];
        float a3 = g_adst[c3 * HEADS + h];
        uint2 r0 = *reinterpret_cast<const uint2*>(g_xw2 + (size_t)c0 * 64 + loff);
        uint2 r1 = *reinterpret_cast<const uint2*>(g_xw2 + (size_t)c1 * 64 + loff);
        uint2 r2 = *reinterpret_cast<const uint2*>(g_xw2 + (size_t)c2 * 64 + loff);
        uint2 r3 = *reinterpret_cast<const uint2*>(g_xw2 + (size_t)c3 * 64 + loff);

        float lr0 = asrc_h + a0; lr0 = lr0 > 0.f ? lr0 : 0.2f * lr0;
        float lr1 = asrc_h + a1; lr1 = lr1 > 0.f ? lr1 : 0.2f * lr1;
        float lr2 = asrc_h + a2; lr2 = lr2 > 0.f ? lr2 : 0.2f * lr2;
        float lr3 = asrc_h + a3; lr3 = lr3 > 0.f ? lr3 : 0.2f * lr3;
        float e0 = __expf(lr0), e1 = __expf(lr1), e2 = __expf(lr2), e3 = __expf(lr3);
        asum += (e0 + e1) + (e2 + e3);

        float2 f;
        f = __half22float2(*reinterpret_cast<__half2*>(&r0.x)); acc.x += e0 * f.x; acc.y += e0 * f.y;
        f = __half22float2(*reinterpret_cast<__half2*>(&r0.y)); acc.z += e0 * f.x; acc.w += e0 * f.y;
        f = __half22float2(*reinterpret_cast<__half2*>(&r1.x)); acc.x += e1 * f.x; acc.y += e1 * f.y;
        f = __half22float2(*reinterpret_cast<__half2*>(&r1.y)); acc.z += e1 * f.x; acc.w += e1 * f.y;
        f = __half22float2(*reinterpret_cast<__half2*>(&r2.x)); acc.x += e2 * f.x; acc.y += e2 * f.y;
        f = __half22float2(*reinterpret_cast<__half2*>(&r2.y)); acc.z += e2 * f.x; acc.w += e2 * f.y;
        f = __half22float2(*reinterpret_cast<__half2*>(&r3.x)); acc.x += e3 * f.x; acc.y += e3 * f.y;
        f = __half22float2(*reinterpret_cast<__half2*>(&r3.y)); acc.z += e3 * f.x; acc.w += e3 * f.y;
    }
    for (; j < deg; ++j) {
        int c = g_scol[start + j];
        float lr = asrc_h + g_adst[c * HEADS + h];
        lr = lr > 0.f ? lr : 0.2f * lr;
        float ex = __expf(lr);
        uint2 raw = *reinterpret_cast<const uint2*>(g_xw2 + (size_t)c * 64 + loff);
        float2 f0 = __half22float2(*reinterpret_cast<__half2*>(&raw.x));
        float2 f1 = __half22float2(*reinterpret_cast<__half2*>(&raw.y));
        acc.x += ex * f0.x; acc.y += ex * f0.y;
        acc.z += ex * f1.x; acc.w += ex * f1.y;
        asum  += ex;
    }
    float inv = 1.f / (asum + 1e-16f);
    acc.x *= inv; acc.y *= inv; acc.z *= inv; acc.w *= inv;
    *reinterpret_cast<float4*>(out + (size_t)n * C_OUT + lane * 4) = acc;
}

extern "C" void kernel_launch(void* const* d_in, const int* in_sizes, int n_in,
                              void* d_out, int out_size)
{
    int ix = -1, iw = -1, ia1 = -1, ia2 = -1, iei = -1;
    for (int i = 0; i < n_in; ++i) {
        int s = in_sizes[i];
        if      (s == N_NODES * C_IN && ix < 0)  ix = i;
        else if (s == C_IN * C_OUT   && iw < 0)  iw = i;
        else if (s == HEADS * HEAD_D) { if (ia1 < 0) ia1 = i; else if (ia2 < 0) ia2 = i; }
        else if (s == 2 * N_EDGES    && iei < 0) iei = i;
    }
    const float* x   = (const float*)d_in[ix];
    const float* W   = (const float*)d_in[iw];
    const float* as_ = (const float*)d_in[ia1];
    const float* ad_ = (const float*)d_in[ia2];
    const void*  ei  = d_in[iei];
    float*       out = (float*)d_out;

    k_prep<<<(N_NODES + 255) / 256, 256>>>((const unsigned*)ei);
    k_hist<<<(N_EDGES / 4 + 255) / 256, 256>>>(ei);
    k_scan1<<<NBLK_SCAN, SCAN_BS>>>();
    k_scan2<<<1, 256>>>();
    k_scan3<<<(N_NODES + 255) / 256, 256>>>();
    k_gemm_tc<<<(N_NODES + GBM - 1) / GBM, 256>>>(x, W, as_, ad_);
    k_reorder<<<(N_EDGES / 4 + 255) / 256, 256>>>(ei);
    k_csr_agg<<<(N_NODES * 32 + 255) / 256, 256>>>(out);
}